// round 11
// baseline (speedup 1.0000x reference)
#include <cuda_runtime.h>
#include <math.h>

#define BATCH  2
#define SEQLEN 2048
#define H      512
#define NST    64
#define M      6           // virtual (compressed) modes
#define MP     3           // mode pairs (f32x2)
#define TCH    16          // timesteps per chunk (= per warp)
#define NWARP  8           // warps per CTA = chunks per group
#define NGRP   16          // chunk groups per (b,hw) column
#define NCOL   (BATCH * 16) // 32 columns; column = (b, hw)

typedef unsigned long long u64;

// compressed coefficient tables, pair-packed, [pair j][h]
__device__ u64 g_a2[MP * H];
__device__ u64 g_c2[MP * H];
__device__ u64 g_q2[MP * H];   // q   = a^TCH
__device__ u64 g_qi2[MP * H];  // qGi = a^-(TCH*NWARP) = (q^8)^-1
// per-group aggregates: [col][g][j][lane]
__device__ u64 g_R[NCOL * NGRP * MP * 32];
// one flag per (col, g), padded to 128B
__device__ int g_flag[NCOL * NGRP * 32];

// Chebyshev nodes (M=6) over [rsqrt(2), rsqrt(65/64)]
__constant__ float f_node[M] = {
    0.987418f, 0.950516f, 0.886597f, 0.812789f, 0.748868f, 0.711966f
};

__device__ __forceinline__ u64 pack2(float lo, float hi) {
    u64 r; asm("mov.b64 %0, {%1, %2};" : "=l"(r) : "f"(lo), "f"(hi)); return r;
}
__device__ __forceinline__ void unpack2(u64 v, float& lo, float& hi) {
    asm("mov.b64 {%0, %1}, %2;" : "=f"(lo), "=f"(hi) : "l"(v));
}
__device__ __forceinline__ u64 fma2_(u64 a, u64 b, u64 c) {
    u64 d; asm("fma.rn.f32x2 %0, %1, %2, %3;" : "=l"(d) : "l"(a), "l"(b), "l"(c)); return d;
}
__device__ __forceinline__ u64 mul2_(u64 a, u64 b) {
    u64 d; asm("mul.rn.f32x2 %0, %1, %2;" : "=l"(d) : "l"(a), "l"(b)); return d;
}
__device__ __forceinline__ u64 add2_(u64 a, u64 b) {
    u64 d; asm("add.rn.f32x2 %0, %1, %2;" : "=l"(d) : "l"(a), "l"(b)); return d;
}
__device__ __forceinline__ int ld_acq(const int* p) {
    int v; asm volatile("ld.acquire.gpu.s32 %0, [%1];" : "=r"(v) : "l"(p) : "memory"); return v;
}
__device__ __forceinline__ void st_rel(int* p, int v) {
    asm volatile("st.release.gpu.s32 [%0], %1;" :: "l"(p), "r"(v) : "memory");
}

// out = base^e, e in [0,7]
__device__ __forceinline__ void pow3(const u64* base, int e, u64* out) {
    u64 p0 = pack2(1.0f, 1.0f), p1 = p0, p2 = p0;
    u64 b0 = base[0], b1 = base[1], b2 = base[2];
    if (e & 1) { p0 = mul2_(p0, b0); p1 = mul2_(p1, b1); p2 = mul2_(p2, b2); }
    b0 = mul2_(b0, b0); b1 = mul2_(b1, b1); b2 = mul2_(b2, b2);
    if (e & 2) { p0 = mul2_(p0, b0); p1 = mul2_(p1, b1); p2 = mul2_(p2, b2); }
    b0 = mul2_(b0, b0); b1 = mul2_(b1, b1); b2 = mul2_(b2, b2);
    if (e & 4) { p0 = mul2_(p0, b0); p1 = mul2_(p1, b1); p2 = mul2_(p2, b2); }
    out[0] = p0; out[1] = p1; out[2] = p2;
}

// out = base^e, e in [0,15]
__device__ __forceinline__ void pow4(const u64* base, int e, u64* out) {
    u64 p0 = pack2(1.0f, 1.0f), p1 = p0, p2 = p0;
    u64 b0 = base[0], b1 = base[1], b2 = base[2];
    if (e & 1) { p0 = mul2_(p0, b0); p1 = mul2_(p1, b1); p2 = mul2_(p2, b2); }
    b0 = mul2_(b0, b0); b1 = mul2_(b1, b1); b2 = mul2_(b2, b2);
    if (e & 2) { p0 = mul2_(p0, b0); p1 = mul2_(p1, b1); p2 = mul2_(p2, b2); }
    b0 = mul2_(b0, b0); b1 = mul2_(b1, b1); b2 = mul2_(b2, b2);
    if (e & 4) { p0 = mul2_(p0, b0); p1 = mul2_(p1, b1); p2 = mul2_(p2, b2); }
    b0 = mul2_(b0, b0); b1 = mul2_(b1, b1); b2 = mul2_(b2, b2);
    if (e & 8) { p0 = mul2_(p0, b0); p1 = mul2_(p1, b1); p2 = mul2_(p2, b2); }
    out[0] = p0; out[1] = p1; out[2] = p2;
}

// ---------------------------------------------------------------- precompute
__global__ void s4_precomp(const float* __restrict__ B_re,
                           const float* __restrict__ C_re,
                           const float* __restrict__ log_dt)
{
    __shared__ float sc[M][NST + 1];
    __shared__ float sa[M], sq[M], sqi[M], scc[M];

    const int n = threadIdx.x;      // 0..63 (true mode)
    const int h = blockIdx.x;

    if (h == 0) {
        for (int i = n; i < NCOL * NGRP; i += NST)
            g_flag[i * 32] = 0;
    }

    const float delta = expf(log_dt[h]);
    const float An = rsqrtf(1.0f + (float)(n + 1) * (1.0f / 64.0f));
    const float cn = expm1f(delta * An) * B_re[n] * delta * C_re[n];

#pragma unroll
    for (int m = 0; m < M; ++m) {
        float num = 1.0f, den = 1.0f;
#pragma unroll
        for (int i = 0; i < M; ++i) {
            if (i == m) continue;
            num *= (An - f_node[i]);
            den *= (f_node[m] - f_node[i]);
        }
        sc[m][n] = cn * (num / den);
    }
    __syncthreads();

    if (n < M) {
        float s = 0.0f;
#pragma unroll
        for (int i = 0; i < NST; ++i) s += sc[n][i];
        scc[n] = s;
        const float dAm = delta * f_node[n];
        sa[n]  = expf(dAm);
        sq[n]  = expf(dAm * (float)TCH);
        sqi[n] = expf(-dAm * (float)(TCH * NWARP));
    }
    __syncthreads();

    if (n < MP) {
        g_a2[n * H + h]  = pack2(sa[2 * n],  sa[2 * n + 1]);
        g_c2[n * H + h]  = pack2(scc[2 * n], scc[2 * n + 1]);
        g_q2[n * H + h]  = pack2(sq[2 * n],  sq[2 * n + 1]);
        g_qi2[n * H + h] = pack2(sqi[2 * n], sqi[2 * n + 1]);
    }
}

// ------------------------------------------------------------------ fused
// CTA = (column, group); warp w = chunk g*8+w (16 timesteps). Register-lean:
// u is NOT kept across the carry phase (reloaded from L2 for the output scan)
// so occupancy reaches 4 CTAs/SM -> 512 CTAs = one wave. PDL overlaps the
// precomp kernel with this kernel's launch + u loads.
__global__ __launch_bounds__(256, 4)
void s4_fused(const float* __restrict__ u,
              const float* __restrict__ Dp,
              float* __restrict__ y)
{
    __shared__ u64 sE [NWARP][MP][32];
    __shared__ u64 sEq[NWARP][MP][32];

    const int col  = blockIdx.x & (NCOL - 1);   // (b, hw)
    const int g    = blockIdx.x >> 5;           // group; lower g = lower bid
    const int w    = threadIdx.x >> 5;
    const int lane = threadIdx.x & 31;
    const int b    = col >> 4;
    const int h    = (col & 15) * 32 + lane;

    const int chunk = g * NWARP + w;
    const size_t base = ((size_t)b * SEQLEN + (size_t)chunk * TCH) * H + h;
    const float* ub = u + base;

    // phase A: u loads do NOT depend on precomp — issue before the PDL sync
    float uu[TCH];
#pragma unroll
    for (int t = 0; t < TCH; ++t) uu[t] = ub[(size_t)t * H];

    cudaGridDependencySynchronize();   // precomp results + flag reset visible

    u64 a[MP], q[MP];
#pragma unroll
    for (int j = 0; j < MP; ++j) {
        a[j] = g_a2[j * H + h];
        q[j] = g_q2[j * H + h];
    }

    // local zero-seed scan -> E
    u64 z[MP] = {0ull, 0ull, 0ull};
#pragma unroll
    for (int t = 0; t < TCH; ++t) {
        const u64 ubb = pack2(uu[t], uu[t]);
        z[0] = fma2_(a[0], z[0], ubb);
        z[1] = fma2_(a[1], z[1], ubb);
        z[2] = fma2_(a[2], z[2], ubb);
    }

    // stage E and q^{7-w} E for the publish add-tree
    {
        u64 qw7[MP];
        pow3(q, (NWARP - 1) - w, qw7);
#pragma unroll
        for (int j = 0; j < MP; ++j) {
            sE [w][j][lane] = z[j];
            sEq[w][j][lane] = mul2_(qw7[j], z[j]);
        }
    }
    __syncthreads();    // the ONLY block-wide sync

    // warp 7: publish R_g = sum_i q^{7-i} E_i
    if (w == NWARP - 1 && g < NGRP - 1) {
        u64* op = g_R + ((size_t)(col * NGRP + g) * MP) * 32 + lane;
#pragma unroll
        for (int j = 0; j < MP; ++j) {
            const u64 s01 = add2_(sEq[0][j][lane], sEq[1][j][lane]);
            const u64 s23 = add2_(sEq[2][j][lane], sEq[3][j][lane]);
            const u64 s45 = add2_(sEq[4][j][lane], sEq[5][j][lane]);
            const u64 s67 = add2_(sEq[6][j][lane], sEq[7][j][lane]);
            op[(size_t)j * 32] = add2_(add2_(s01, s23), add2_(s45, s67));
        }
        __syncwarp();
        if (lane == 0) st_rel(&g_flag[(col * NGRP + g) * 32], 1);
    }

    // P_w = sum_{i<w} q^{w-1-i} E_i
    u64 P[MP] = {0ull, 0ull, 0ull};
    for (int i = 0; i < w; ++i) {
#pragma unroll
        for (int j = 0; j < MP; ++j)
            P[j] = fma2_(q[j], P[j], sE[i][j][lane]);
    }
    u64 qp[MP];
    pow3(q, w, qp);

    // per-warp receive: S = sum_{g2<g} qG^{g-1-g2} R_{g2}, qG = q^8
    u64 S[MP] = {0ull, 0ull, 0ull};
    if (g > 0) {
        if (lane < g) {
            const int* fp = &g_flag[(col * NGRP + lane) * 32];
            while (ld_acq(fp) == 0) { __nanosleep(20); }
        }
        __syncwarp();

        u64 qG[MP];
#pragma unroll
        for (int j = 0; j < MP; ++j) {
            const u64 q2v = mul2_(q[j], q[j]);
            const u64 q4v = mul2_(q2v, q2v);
            qG[j] = mul2_(q4v, q4v);
        }
        // T = sum_{g2=0}^{14} qG^{14-g2} V_{g2} = qG^{15-g} S   (V = R if g2<g)
        u64 T[MP] = {0ull, 0ull, 0ull};
#pragma unroll
        for (int g2 = 0; g2 < NGRP - 1; ++g2) {
            u64 v0 = 0ull, v1 = 0ull, v2 = 0ull;
            if (g2 < g) {
                const u64* rp = g_R + ((size_t)(col * NGRP + g2) * MP) * 32 + lane;
                v0 = rp[0 * 32];
                v1 = rp[1 * 32];
                v2 = rp[2 * 32];
            }
            T[0] = fma2_(qG[0], T[0], v0);
            T[1] = fma2_(qG[1], T[1], v1);
            T[2] = fma2_(qG[2], T[2], v2);
        }
        // S = T * qGi^{15-g}
        u64 qGi[MP];
#pragma unroll
        for (int j = 0; j < MP; ++j) qGi[j] = g_qi2[j * H + h];
        u64 pw[MP];
        pow4(qGi, (NGRP - 1) - g, pw);
#pragma unroll
        for (int j = 0; j < MP; ++j) S[j] = mul2_(T[j], pw[j]);
    }

    // seed and output scan; u reloaded (L2-resident), y written exactly once
    u64 zz[MP];
#pragma unroll
    for (int j = 0; j < MP; ++j) zz[j] = fma2_(qp[j], S[j], P[j]);

    u64 c[MP];
#pragma unroll
    for (int j = 0; j < MP; ++j) c[j] = g_c2[j * H + h];
    const float Dh = Dp[h];

    float uo[TCH];
#pragma unroll
    for (int t = 0; t < TCH; ++t) uo[t] = ub[(size_t)t * H];

    float* yb = y + base;
#pragma unroll
    for (int t = 0; t < TCH; ++t) {
        const u64 ubb = pack2(uo[t], uo[t]);
        zz[0] = fma2_(a[0], zz[0], ubb);
        zz[1] = fma2_(a[1], zz[1], ubb);
        zz[2] = fma2_(a[2], zz[2], ubb);
        u64 ac0 = fma2_(c[0], zz[0], 0ull);
        u64 ac1 = fma2_(c[1], zz[1], 0ull);
        ac0 = fma2_(c[2], zz[2], ac0);
        const u64 sSum = add2_(ac0, ac1);
        float x0, x1; unpack2(sSum, x0, x1);
        yb[(size_t)t * H] = fmaf(Dh, uo[t], x0 + x1);
    }
}

extern "C" void kernel_launch(void* const* d_in, const int* in_sizes, int n_in,
                              void* d_out, int out_size)
{
    const float* u      = (const float*)d_in[0];
    const float* B_re   = (const float*)d_in[1];
    const float* C_re   = (const float*)d_in[2];
    const float* log_dt = (const float*)d_in[3];
    const float* Dp     = (const float*)d_in[4];
    float* y = (float*)d_out;

    s4_precomp<<<H, NST>>>(B_re, C_re, log_dt);

    // PDL: fused launches immediately; its pre-sync section (u loads) overlaps
    // the precomp kernel. cudaGridDependencySynchronize() gates coeff reads.
    cudaLaunchConfig_t cfg = {};
    cfg.gridDim  = dim3(NCOL * NGRP, 1, 1);
    cfg.blockDim = dim3(NWARP * 32, 1, 1);
    cudaLaunchAttribute at[1];
    at[0].id = cudaLaunchAttributeProgrammaticStreamSerialization;
    at[0].val.programmaticStreamSerializationAllowed = 1;
    cfg.attrs = at;
    cfg.numAttrs = 1;
    cudaLaunchKernelEx(&cfg, s4_fused, u, Dp, y);
}

// round 12
// speedup vs baseline: 1.2712x; 1.2712x over previous
#include <cuda_runtime.h>
#include <math.h>

#define BATCH  2
#define SEQLEN 2048
#define H      512
#define NST    64
#define M      6           // virtual (compressed) modes
#define MP     3           // mode pairs (f32x2)
#define TCH    32          // timesteps per chunk (= per warp)
#define NWARP  8           // warps per CTA = chunks per group
#define NGRP   8           // chunk groups per (b,hw) column
#define NCOL   (BATCH * 16) // 32 columns; column = (b, hw)

typedef unsigned long long u64;

// compressed coefficient tables, pair-packed, [pair j][h]
__device__ u64 g_a2[MP * H];
__device__ u64 g_c2[MP * H];
__device__ u64 g_q2[MP * H];   // q   = a^TCH
__device__ u64 g_qi2[MP * H];  // qi8 = a^-(TCH*NWARP) = (q^8)^-1
// per-group aggregates: [col][g][j][lane]
__device__ u64 g_R[NCOL * NGRP * MP * 32];
// one flag per (col, g), padded to 128B
__device__ int g_flag[NCOL * NGRP * 32];

// Chebyshev nodes (M=6) over [rsqrt(2), rsqrt(65/64)]
__constant__ float f_node[M] = {
    0.987418f, 0.950516f, 0.886597f, 0.812789f, 0.748868f, 0.711966f
};

__device__ __forceinline__ u64 pack2(float lo, float hi) {
    u64 r; asm("mov.b64 %0, {%1, %2};" : "=l"(r) : "f"(lo), "f"(hi)); return r;
}
__device__ __forceinline__ void unpack2(u64 v, float& lo, float& hi) {
    asm("mov.b64 {%0, %1}, %2;" : "=f"(lo), "=f"(hi) : "l"(v));
}
__device__ __forceinline__ u64 fma2_(u64 a, u64 b, u64 c) {
    u64 d; asm("fma.rn.f32x2 %0, %1, %2, %3;" : "=l"(d) : "l"(a), "l"(b), "l"(c)); return d;
}
__device__ __forceinline__ u64 mul2_(u64 a, u64 b) {
    u64 d; asm("mul.rn.f32x2 %0, %1, %2;" : "=l"(d) : "l"(a), "l"(b)); return d;
}
__device__ __forceinline__ u64 add2_(u64 a, u64 b) {
    u64 d; asm("add.rn.f32x2 %0, %1, %2;" : "=l"(d) : "l"(a), "l"(b)); return d;
}
__device__ __forceinline__ int ld_acq(const int* p) {
    int v; asm volatile("ld.acquire.gpu.s32 %0, [%1];" : "=r"(v) : "l"(p) : "memory"); return v;
}
__device__ __forceinline__ void st_rel(int* p, int v) {
    asm volatile("st.release.gpu.s32 [%0], %1;" :: "l"(p), "r"(v) : "memory");
}

// out = base^e (e in [0,7]) per pair, repeated squaring
__device__ __forceinline__ void pow3(const u64* base, int e, u64* out) {
    u64 p0 = pack2(1.0f, 1.0f), p1 = p0, p2 = p0;
    u64 b0 = base[0], b1 = base[1], b2 = base[2];
    if (e & 1) { p0 = mul2_(p0, b0); p1 = mul2_(p1, b1); p2 = mul2_(p2, b2); }
    b0 = mul2_(b0, b0); b1 = mul2_(b1, b1); b2 = mul2_(b2, b2);
    if (e & 2) { p0 = mul2_(p0, b0); p1 = mul2_(p1, b1); p2 = mul2_(p2, b2); }
    b0 = mul2_(b0, b0); b1 = mul2_(b1, b1); b2 = mul2_(b2, b2);
    if (e & 4) { p0 = mul2_(p0, b0); p1 = mul2_(p1, b1); p2 = mul2_(p2, b2); }
    out[0] = p0; out[1] = p1; out[2] = p2;
}

// ---------------------------------------------------------------- precompute
// One block per channel h; all float. Also resets carry flags.
__global__ void s4_precomp(const float* __restrict__ B_re,
                           const float* __restrict__ C_re,
                           const float* __restrict__ log_dt)
{
    __shared__ float sc[M][NST + 1];
    __shared__ float sa[M], sq[M], sqi[M], scc[M];

    const int n = threadIdx.x;      // 0..63 (true mode)
    const int h = blockIdx.x;

    if (h == 0) {
        for (int i = n; i < NCOL * NGRP; i += NST)
            g_flag[i * 32] = 0;
    }

    const float delta = expf(log_dt[h]);
    const float An = rsqrtf(1.0f + (float)(n + 1) * (1.0f / 64.0f));
    const float cn = expm1f(delta * An) * B_re[n] * delta * C_re[n];

#pragma unroll
    for (int m = 0; m < M; ++m) {
        float num = 1.0f, den = 1.0f;
#pragma unroll
        for (int i = 0; i < M; ++i) {
            if (i == m) continue;
            num *= (An - f_node[i]);
            den *= (f_node[m] - f_node[i]);
        }
        sc[m][n] = cn * (num / den);
    }
    __syncthreads();

    if (n < M) {
        float s = 0.0f;
#pragma unroll
        for (int i = 0; i < NST; ++i) s += sc[n][i];
        scc[n] = s;
        const float dAm = delta * f_node[n];
        sa[n]  = expf(dAm);
        sq[n]  = expf(dAm * (float)TCH);
        sqi[n] = expf(-dAm * (float)(TCH * NWARP));
    }
    __syncthreads();

    if (n < MP) {
        g_a2[n * H + h]  = pack2(sa[2 * n],  sa[2 * n + 1]);
        g_c2[n * H + h]  = pack2(scc[2 * n], scc[2 * n + 1]);
        g_q2[n * H + h]  = pack2(sq[2 * n],  sq[2 * n + 1]);
        g_qi2[n * H + h] = pack2(sqi[2 * n], sqi[2 * n + 1]);
    }
}

// ------------------------------------------------------------------ fused
// R10 structure (best known): CTA = (column, group); warp w = chunk g*8+w,
// TCH=32, u resident in registers, ONE __syncthreads, warp-7 add-tree publish,
// per-warp parallel receive. PDL overlaps precomp with the u-load phase.
__global__ __launch_bounds__(256, 2)
void s4_fused(const float* __restrict__ u,
              const float* __restrict__ Dp,
              float* __restrict__ y)
{
    __shared__ u64 sE [NWARP][MP][32];
    __shared__ u64 sEq[NWARP][MP][32];

    const int col  = blockIdx.x & (NCOL - 1);   // (b, hw)
    const int g    = blockIdx.x >> 5;           // group; lower g = lower bid
    const int w    = threadIdx.x >> 5;
    const int lane = threadIdx.x & 31;
    const int b    = col >> 4;
    const int h    = (col & 15) * 32 + lane;

    const int chunk = g * NWARP + w;
    const size_t base = ((size_t)b * SEQLEN + (size_t)chunk * TCH) * H + h;
    const float* ub = u + base;

    // phase A (pre-PDL-sync): u loads don't depend on precomp
    float uu[TCH];
#pragma unroll
    for (int t = 0; t < TCH; ++t) uu[t] = ub[(size_t)t * H];

    cudaGridDependencySynchronize();   // precomp tables + flag reset visible

    u64 a[MP], c[MP], q[MP];
#pragma unroll
    for (int j = 0; j < MP; ++j) {
        a[j] = g_a2[j * H + h];
        c[j] = g_c2[j * H + h];
        q[j] = g_q2[j * H + h];
    }
    const float Dh = Dp[h];

    // local zero-seed scan -> E (chunk impulse state)
    u64 z[MP] = {0ull, 0ull, 0ull};
#pragma unroll
    for (int t = 0; t < TCH; ++t) {
        const u64 ubb = pack2(uu[t], uu[t]);
        z[0] = fma2_(a[0], z[0], ubb);
        z[1] = fma2_(a[1], z[1], ubb);
        z[2] = fma2_(a[2], z[2], ubb);
    }

    // stage E and q^{7-w} * E (pre-scaled for the publish add-tree)
    {
        u64 qw7[MP];
        pow3(q, (NWARP - 1) - w, qw7);
#pragma unroll
        for (int j = 0; j < MP; ++j) {
            sE [w][j][lane] = z[j];
            sEq[w][j][lane] = mul2_(qw7[j], z[j]);
        }
    }
    __syncthreads();    // the ONLY block-wide sync

    // warp 7: publish R_g = sum_i q^{7-i} E_i via add-tree (MLP'd LDS)
    if (w == NWARP - 1 && g < NGRP - 1) {
        u64* op = g_R + ((size_t)(col * NGRP + g) * MP) * 32 + lane;
#pragma unroll
        for (int j = 0; j < MP; ++j) {
            const u64 s01 = add2_(sEq[0][j][lane], sEq[1][j][lane]);
            const u64 s23 = add2_(sEq[2][j][lane], sEq[3][j][lane]);
            const u64 s45 = add2_(sEq[4][j][lane], sEq[5][j][lane]);
            const u64 s67 = add2_(sEq[6][j][lane], sEq[7][j][lane]);
            op[(size_t)j * 32] = add2_(add2_(s01, s23), add2_(s45, s67));
        }
        __syncwarp();
        if (lane == 0) st_rel(&g_flag[(col * NGRP + g) * 32], 1);
    }

    // P_w = sum_{i<w} q^{w-1-i} E_i  (intra-group Horner over smem)
    u64 P[MP] = {0ull, 0ull, 0ull};
    for (int i = 0; i < w; ++i) {
#pragma unroll
        for (int j = 0; j < MP; ++j)
            P[j] = fma2_(q[j], P[j], sE[i][j][lane]);
    }
    u64 qp[MP];
    pow3(q, w, qp);

    // per-warp receive: S = sum_{g2<g} q8^{g-1-g2} R_{g2}
    u64 S[MP] = {0ull, 0ull, 0ull};
    if (g > 0) {
        // parallel flag polls: lane i waits on flag i
        if (lane < g) {
            const int* fp = &g_flag[(col * NGRP + lane) * 32];
            while (ld_acq(fp) == 0) { __nanosleep(20); }
        }
        __syncwarp();

        u64 q8[MP];
#pragma unroll
        for (int j = 0; j < MP; ++j) {
            const u64 q2v = mul2_(q[j], q[j]);
            const u64 q4v = mul2_(q2v, q2v);
            q8[j] = mul2_(q4v, q4v);
        }
        // fixed unrolled predicated Horner: T = q8^{7-g} * S
        u64 T[MP] = {0ull, 0ull, 0ull};
#pragma unroll
        for (int g2 = 0; g2 < NGRP - 1; ++g2) {
            u64 v0 = 0ull, v1 = 0ull, v2 = 0ull;
            if (g2 < g) {
                const u64* rp = g_R + ((size_t)(col * NGRP + g2) * MP) * 32 + lane;
                v0 = rp[0 * 32];
                v1 = rp[1 * 32];
                v2 = rp[2 * 32];
            }
            T[0] = fma2_(q8[0], T[0], v0);
            T[1] = fma2_(q8[1], T[1], v1);
            T[2] = fma2_(q8[2], T[2], v2);
        }
        // S = T * qi8^{7-g}
        u64 qi8[MP];
#pragma unroll
        for (int j = 0; j < MP; ++j) qi8[j] = g_qi2[j * H + h];
        u64 pw[MP];
        pow3(qi8, (NGRP - 1) - g, pw);
#pragma unroll
        for (int j = 0; j < MP; ++j) S[j] = mul2_(T[j], pw[j]);
    }

    // seed = q^w * S + P_w, then output scan (writes y exactly once)
    u64 zz[MP];
#pragma unroll
    for (int j = 0; j < MP; ++j) zz[j] = fma2_(qp[j], S[j], P[j]);

    float* yb = y + base;
#pragma unroll
    for (int t = 0; t < TCH; ++t) {
        const u64 ubb = pack2(uu[t], uu[t]);
        zz[0] = fma2_(a[0], zz[0], ubb);
        zz[1] = fma2_(a[1], zz[1], ubb);
        zz[2] = fma2_(a[2], zz[2], ubb);
        u64 ac0 = fma2_(c[0], zz[0], 0ull);
        u64 ac1 = fma2_(c[1], zz[1], 0ull);
        ac0 = fma2_(c[2], zz[2], ac0);
        const u64 sSum = add2_(ac0, ac1);
        float x0, x1; unpack2(sSum, x0, x1);
        yb[(size_t)t * H] = fmaf(Dh, uu[t], x0 + x1);
    }
}

extern "C" void kernel_launch(void* const* d_in, const int* in_sizes, int n_in,
                              void* d_out, int out_size)
{
    const float* u      = (const float*)d_in[0];
    const float* B_re   = (const float*)d_in[1];
    const float* C_re   = (const float*)d_in[2];
    const float* log_dt = (const float*)d_in[3];
    const float* Dp     = (const float*)d_in[4];
    float* y = (float*)d_out;

    s4_precomp<<<H, NST>>>(B_re, C_re, log_dt);

    // PDL: fused's pre-sync section (u loads) overlaps precomp + launch gap.
    cudaLaunchConfig_t cfg = {};
    cfg.gridDim  = dim3(NCOL * NGRP, 1, 1);
    cfg.blockDim = dim3(NWARP * 32, 1, 1);
    cudaLaunchAttribute at[1];
    at[0].id = cudaLaunchAttributeProgrammaticStreamSerialization;
    at[0].val.programmaticStreamSerializationAllowed = 1;
    cfg.attrs = at;
    cfg.numAttrs = 1;
    cudaLaunchKernelEx(&cfg, s4_fused, u, Dp, y);
}

// round 13
// speedup vs baseline: 1.2959x; 1.0194x over previous
#include <cuda_runtime.h>
#include <math.h>

#define BATCH  2
#define SEQLEN 2048
#define H      512
#define NST    64
#define M      6           // virtual (compressed) modes
#define MP     3           // mode pairs (f32x2)
#define TCH    32          // timesteps per chunk (= per warp)
#define NWARP  8           // warps per CTA = chunks per group
#define NGRP   8           // chunk groups per (b,hw) column
#define NCOL   (BATCH * 16) // 32 columns; column = (b, hw)

typedef unsigned long long u64;

// per-group aggregates: [col][g][j][lane]
__device__ u64 g_R[NCOL * NGRP * MP * 32];
// one flag per (col, g), padded to 128B; zeroed by a memset node each launch
__device__ int g_flag[NCOL * NGRP * 32];

// Chebyshev nodes (M=6) over [rsqrt(2), rsqrt(65/64)]
__constant__ float f_node[M] = {
    0.987418f, 0.950516f, 0.886597f, 0.812789f, 0.748868f, 0.711966f
};

__device__ __forceinline__ u64 pack2(float lo, float hi) {
    u64 r; asm("mov.b64 %0, {%1, %2};" : "=l"(r) : "f"(lo), "f"(hi)); return r;
}
__device__ __forceinline__ void unpack2(u64 v, float& lo, float& hi) {
    asm("mov.b64 {%0, %1}, %2;" : "=f"(lo), "=f"(hi) : "l"(v));
}
__device__ __forceinline__ u64 fma2_(u64 a, u64 b, u64 c) {
    u64 d; asm("fma.rn.f32x2 %0, %1, %2, %3;" : "=l"(d) : "l"(a), "l"(b), "l"(c)); return d;
}
__device__ __forceinline__ u64 mul2_(u64 a, u64 b) {
    u64 d; asm("mul.rn.f32x2 %0, %1, %2;" : "=l"(d) : "l"(a), "l"(b)); return d;
}
__device__ __forceinline__ u64 add2_(u64 a, u64 b) {
    u64 d; asm("add.rn.f32x2 %0, %1, %2;" : "=l"(d) : "l"(a), "l"(b)); return d;
}
__device__ __forceinline__ int ld_acq(const int* p) {
    int v; asm volatile("ld.acquire.gpu.s32 %0, [%1];" : "=r"(v) : "l"(p) : "memory"); return v;
}
__device__ __forceinline__ void st_rel(int* p, int v) {
    asm volatile("st.release.gpu.s32 [%0], %1;" :: "l"(p), "r"(v) : "memory");
}

// out = base^e (e in [0,7]) per pair, repeated squaring
__device__ __forceinline__ void pow3(const u64* base, int e, u64* out) {
    u64 p0 = pack2(1.0f, 1.0f), p1 = p0, p2 = p0;
    u64 b0 = base[0], b1 = base[1], b2 = base[2];
    if (e & 1) { p0 = mul2_(p0, b0); p1 = mul2_(p1, b1); p2 = mul2_(p2, b2); }
    b0 = mul2_(b0, b0); b1 = mul2_(b1, b1); b2 = mul2_(b2, b2);
    if (e & 2) { p0 = mul2_(p0, b0); p1 = mul2_(p1, b1); p2 = mul2_(p2, b2); }
    b0 = mul2_(b0, b0); b1 = mul2_(b1, b1); b2 = mul2_(b2, b2);
    if (e & 4) { p0 = mul2_(p0, b0); p1 = mul2_(p1, b1); p2 = mul2_(p2, b2); }
    out[0] = p0; out[1] = p1; out[2] = p2;
}

// ------------------------------------------------------------------ fused
// Single kernel. CTA = (column, group); warp w = chunk g*8+w, TCH=32.
// Coefficients computed PER CTA in smem during the u-load DRAM burst
// (Taylor expm1/exp for x<=1e-3 -> almost no MUFU; Lagrange table h-indep).
// Then: R10-structure scan / one __syncthreads / warp-7 add-tree publish /
// per-warp parallel receive via flags (zeroed by a memset graph node).
__global__ __launch_bounds__(256, 2)
void s4_fused(const float* __restrict__ u,
              const float* __restrict__ Dp,
              float* __restrict__ y,
              const float* __restrict__ B_re,
              const float* __restrict__ C_re,
              const float* __restrict__ log_dt)
{
    __shared__ u64   sE [NWARP][MP][32];
    __shared__ u64   sEq[NWARP][MP][32];
    __shared__ float sL[NST][M];          // Lagrange basis at true modes
    __shared__ float sAn[NST];            // A_n values
    __shared__ float sDelta[32];          // delta per local h
    __shared__ float sPart[8][32][M];     // c~ partial sums per k-group
    __shared__ float sA[32][M], sC[32][M], sQ[32][M], sQI[32][M];

    const int tid  = threadIdx.x;
    const int col  = blockIdx.x & (NCOL - 1);   // (b, hw)
    const int g    = blockIdx.x >> 5;           // group; lower g = lower bid
    const int w    = tid >> 5;
    const int lane = tid & 31;
    const int b    = col >> 4;
    const int hw   = col & 15;
    const int h    = hw * 32 + lane;

    const int chunk = g * NWARP + w;
    const size_t base = ((size_t)b * SEQLEN + (size_t)chunk * TCH) * H + h;
    const float* ub = u + base;

    // ---- phase A: issue ALL u loads first (DRAM burst starts immediately)
    float uu[TCH];
#pragma unroll
    for (int t = 0; t < TCH; ++t) uu[t] = ub[(size_t)t * H];

    // ---- phase B: coefficients, hidden under the load burst ----
    if (tid < NST) {
        const float An = rsqrtf(1.0f + (float)(tid + 1) * (1.0f / 64.0f));
        sAn[tid] = An;
#pragma unroll
        for (int m = 0; m < M; ++m) {
            float num = 1.0f, den = 1.0f;
#pragma unroll
            for (int i = 0; i < M; ++i) {
                if (i == m) continue;
                num *= (An - f_node[i]);
                den *= (f_node[m] - f_node[i]);
            }
            sL[tid][m] = num / den;
        }
    }
    if (tid < 32) sDelta[tid] = expf(log_dt[hw * 32 + tid]);
    __syncthreads();

    {
        const int k  = tid >> 5;   // 0..7: true-mode octet
        const int hl = tid & 31;
        const float delta = sDelta[hl];
        float cm[M] = {0.0f, 0.0f, 0.0f, 0.0f, 0.0f, 0.0f};
#pragma unroll
        for (int i = 0; i < 8; ++i) {
            const int n = k * 8 + i;
            const float x = delta * sAn[n];                       // <= 1e-3
            const float em = x * fmaf(x, fmaf(x, (1.0f / 6.0f), 0.5f), 1.0f); // expm1
            const float cn = em * B_re[n] * delta * C_re[n];
#pragma unroll
            for (int m = 0; m < M; ++m)
                cm[m] = fmaf(cn, sL[n][m], cm[m]);
        }
#pragma unroll
        for (int m = 0; m < M; ++m) sPart[k][hl][m] = cm[m];

        if (k < M) {   // (hl, m=k): a, q=a^32, qi=q^-8
            const float x = delta * f_node[k];                    // <= 1e-3
            const float am = 1.0f + x * fmaf(x, fmaf(x, (1.0f / 6.0f), 0.5f), 1.0f);
            float qm = am;
#pragma unroll
            for (int s = 0; s < 5; ++s) qm *= qm;                 // a^32
            float q8 = qm;
#pragma unroll
            for (int s = 0; s < 3; ++s) q8 *= q8;                 // a^256
            sA[hl][k]  = am;
            sQ[hl][k]  = qm;
            sQI[hl][k] = 1.0f / q8;
        }
    }
    __syncthreads();
    if (tid < 32 * M) {   // reduce c~ over the 8 octets
        const int hl = tid & 31, m = tid >> 5;
        float s = 0.0f;
#pragma unroll
        for (int k = 0; k < 8; ++k) s += sPart[k][hl][m];
        sC[hl][m] = s;
    }
    __syncthreads();

    u64 a[MP], c[MP], q[MP];
#pragma unroll
    for (int j = 0; j < MP; ++j) {
        a[j] = pack2(sA[lane][2 * j], sA[lane][2 * j + 1]);
        c[j] = pack2(sC[lane][2 * j], sC[lane][2 * j + 1]);
        q[j] = pack2(sQ[lane][2 * j], sQ[lane][2 * j + 1]);
    }
    const float Dh = Dp[h];

    // ---- local zero-seed scan -> E (chunk impulse state) ----
    u64 z[MP] = {0ull, 0ull, 0ull};
#pragma unroll
    for (int t = 0; t < TCH; ++t) {
        const u64 ubb = pack2(uu[t], uu[t]);
        z[0] = fma2_(a[0], z[0], ubb);
        z[1] = fma2_(a[1], z[1], ubb);
        z[2] = fma2_(a[2], z[2], ubb);
    }

    // stage E and q^{7-w} * E (pre-scaled for the publish add-tree)
    {
        u64 qw7[MP];
        pow3(q, (NWARP - 1) - w, qw7);
#pragma unroll
        for (int j = 0; j < MP; ++j) {
            sE [w][j][lane] = z[j];
            sEq[w][j][lane] = mul2_(qw7[j], z[j]);
        }
    }
    __syncthreads();

    // warp 7: publish R_g = sum_i q^{7-i} E_i via add-tree
    if (w == NWARP - 1 && g < NGRP - 1) {
        u64* op = g_R + ((size_t)(col * NGRP + g) * MP) * 32 + lane;
#pragma unroll
        for (int j = 0; j < MP; ++j) {
            const u64 s01 = add2_(sEq[0][j][lane], sEq[1][j][lane]);
            const u64 s23 = add2_(sEq[2][j][lane], sEq[3][j][lane]);
            const u64 s45 = add2_(sEq[4][j][lane], sEq[5][j][lane]);
            const u64 s67 = add2_(sEq[6][j][lane], sEq[7][j][lane]);
            op[(size_t)j * 32] = add2_(add2_(s01, s23), add2_(s45, s67));
        }
        __syncwarp();
        if (lane == 0) st_rel(&g_flag[(col * NGRP + g) * 32], 1);
    }

    // P_w = sum_{i<w} q^{w-1-i} E_i
    u64 P[MP] = {0ull, 0ull, 0ull};
    for (int i = 0; i < w; ++i) {
#pragma unroll
        for (int j = 0; j < MP; ++j)
            P[j] = fma2_(q[j], P[j], sE[i][j][lane]);
    }
    u64 qp[MP];
    pow3(q, w, qp);

    // per-warp receive: S = sum_{g2<g} q8^{g-1-g2} R_{g2}
    u64 S[MP] = {0ull, 0ull, 0ull};
    if (g > 0) {
        if (lane < g) {
            const int* fp = &g_flag[(col * NGRP + lane) * 32];
            while (ld_acq(fp) == 0) { __nanosleep(20); }
        }
        __syncwarp();

        u64 q8[MP];
#pragma unroll
        for (int j = 0; j < MP; ++j) {
            const u64 q2v = mul2_(q[j], q[j]);
            const u64 q4v = mul2_(q2v, q2v);
            q8[j] = mul2_(q4v, q4v);
        }
        // fixed unrolled predicated Horner: T = q8^{7-g} * S
        u64 T[MP] = {0ull, 0ull, 0ull};
#pragma unroll
        for (int g2 = 0; g2 < NGRP - 1; ++g2) {
            u64 v0 = 0ull, v1 = 0ull, v2 = 0ull;
            if (g2 < g) {
                const u64* rp = g_R + ((size_t)(col * NGRP + g2) * MP) * 32 + lane;
                v0 = rp[0 * 32];
                v1 = rp[1 * 32];
                v2 = rp[2 * 32];
            }
            T[0] = fma2_(q8[0], T[0], v0);
            T[1] = fma2_(q8[1], T[1], v1);
            T[2] = fma2_(q8[2], T[2], v2);
        }
        // S = T * qi8^{7-g}
        u64 qi8[MP];
#pragma unroll
        for (int j = 0; j < MP; ++j)
            qi8[j] = pack2(sQI[lane][2 * j], sQI[lane][2 * j + 1]);
        u64 pw[MP];
        pow3(qi8, (NGRP - 1) - g, pw);
#pragma unroll
        for (int j = 0; j < MP; ++j) S[j] = mul2_(T[j], pw[j]);
    }

    // seed = q^w * S + P_w, then output scan (writes y exactly once)
    u64 zz[MP];
#pragma unroll
    for (int j = 0; j < MP; ++j) zz[j] = fma2_(qp[j], S[j], P[j]);

    float* yb = y + base;
#pragma unroll
    for (int t = 0; t < TCH; ++t) {
        const u64 ubb = pack2(uu[t], uu[t]);
        zz[0] = fma2_(a[0], zz[0], ubb);
        zz[1] = fma2_(a[1], zz[1], ubb);
        zz[2] = fma2_(a[2], zz[2], ubb);
        u64 ac0 = fma2_(c[0], zz[0], 0ull);
        u64 ac1 = fma2_(c[1], zz[1], 0ull);
        ac0 = fma2_(c[2], zz[2], ac0);
        const u64 sSum = add2_(ac0, ac1);
        float x0, x1; unpack2(sSum, x0, x1);
        yb[(size_t)t * H] = fmaf(Dh, uu[t], x0 + x1);
    }
}

extern "C" void kernel_launch(void* const* d_in, const int* in_sizes, int n_in,
                              void* d_out, int out_size)
{
    const float* u      = (const float*)d_in[0];
    const float* B_re   = (const float*)d_in[1];
    const float* C_re   = (const float*)d_in[2];
    const float* log_dt = (const float*)d_in[3];
    const float* Dp     = (const float*)d_in[4];
    float* y = (float*)d_out;

    // zero the carry flags (graph-capturable async memset; no allocs)
    void* fp = nullptr;
    cudaGetSymbolAddress(&fp, g_flag);
    cudaMemsetAsync(fp, 0, sizeof(int) * NCOL * NGRP * 32);

    s4_fused<<<NCOL * NGRP, NWARP * 32>>>(u, Dp, y, B_re, C_re, log_dt);
}